// round 4
// baseline (speedup 1.0000x reference)
#include <cuda_runtime.h>
#include <cstdint>

#define Tt 1024
#define Bb 64
#define Ii 512
#define Hh 1024
#define Gg 3072
#define Oo 256
#define NCTA 128

// scratch (device globals = allowed scratch)
__device__ float g_gi[(size_t)Tt * Bb * Gg];  // [t][b][g]
__device__ float g_h [(size_t)Tt * Bb * Hh];  // [t][b][k]
__device__ unsigned g_bar_count;
__device__ unsigned g_bar_gen;

typedef unsigned long long u64;

__device__ __forceinline__ u64 pk2(float x, float y) {
    u64 r; asm("mov.b64 %0,{%1,%2};" : "=l"(r) : "f"(x), "f"(y)); return r;
}
__device__ __forceinline__ void f2(u64& d, u64 a, u64 b) {
    asm("fma.rn.f32x2 %0,%1,%2,%0;" : "+l"(d) : "l"(a), "l"(b));
}
__device__ __forceinline__ float2 up2(u64 a) {
    float2 f; asm("mov.b64 {%0,%1},%2;" : "=f"(f.x), "=f"(f.y) : "l"(a)); return f;
}
__device__ __forceinline__ float sigm(float x) { return 1.0f / (1.0f + __expf(-x)); }

__device__ __forceinline__ void cp16(void* smem, const void* g) {
    uint32_t s = (uint32_t)__cvta_generic_to_shared(smem);
    asm volatile("cp.async.cg.shared.global [%0], [%1], 16;" :: "r"(s), "l"(g));
}

__global__ void init_bar() { g_bar_count = 0u; g_bar_gen = 0u; }

// ---------------------------------------------------------------------------
// SGEMM: C[M,N] = A[M,K] @ W[K,N] + bias.  BM=128, BN=64, BK=16, 256 threads,
// thread-tile 8m x 4n (n packed as f32x2 pairs).
// MODE 0: A=X (K=512, ldw=3072), write g_gi[t][b][g] with row r=b*1024+t.
// MODE 1: A=g_h (K=1024, ldw=256), write C=out[b][t][o] with row r=t*64+b.
// ---------------------------------------------------------------------------
template <int K, int MODE>
__global__ __launch_bounds__(256) void sgemm(const float* __restrict__ Ain,
                                             const float* __restrict__ W,
                                             const float* __restrict__ bias,
                                             float* __restrict__ Cout)
{
    __shared__ float As[16][132];
    __shared__ float Bs[16][64];
    const float* A = (MODE == 0) ? Ain : g_h;
    const int ldw = (MODE == 0) ? Gg : Oo;
    const int m0 = blockIdx.y * 128, n0 = blockIdx.x * 64;
    const int tid = threadIdx.x;
    const int tn = tid & 15, tm = tid >> 4;

    u64 acc[8][2];
    #pragma unroll
    for (int m = 0; m < 8; m++) { acc[m][0] = 0ull; acc[m][1] = 0ull; }

    for (int k0 = 0; k0 < K; k0 += 16) {
        #pragma unroll
        for (int i = 0; i < 2; i++) {
            int idx = tid + i * 256;            // 512 float4 = 128 rows x 4
            int r = idx >> 2, kq = idx & 3;
            float4 v = *(const float4*)(A + (size_t)(m0 + r) * K + k0 + kq * 4);
            As[kq * 4 + 0][r] = v.x; As[kq * 4 + 1][r] = v.y;
            As[kq * 4 + 2][r] = v.z; As[kq * 4 + 3][r] = v.w;
        }
        {
            int r = tid >> 4, gq = tid & 15;    // 16 rows x 16 float4
            *(float4*)&Bs[r][gq * 4] =
                *(const float4*)(W + (size_t)(k0 + r) * ldw + n0 + gq * 4);
        }
        __syncthreads();
        #pragma unroll
        for (int k = 0; k < 16; k++) {
            float4 a0 = *(float4*)&As[k][tm * 8];
            float4 a1 = *(float4*)&As[k][tm * 8 + 4];
            u64 b0 = *(u64*)&Bs[k][tn * 4];
            u64 b1 = *(u64*)&Bs[k][tn * 4 + 2];
            float av[8] = {a0.x, a0.y, a0.z, a0.w, a1.x, a1.y, a1.z, a1.w};
            #pragma unroll
            for (int m = 0; m < 8; m++) {
                u64 ad = pk2(av[m], av[m]);
                f2(acc[m][0], ad, b0);
                f2(acc[m][1], ad, b1);
            }
        }
        __syncthreads();
    }

    const int n = n0 + tn * 4;
    float4 bi = *(const float4*)(bias + n);
    #pragma unroll
    for (int m = 0; m < 8; m++) {
        int r = m0 + tm * 8 + m;
        float2 p0 = up2(acc[m][0]), p1 = up2(acc[m][1]);
        float4 o = make_float4(p0.x + bi.x, p0.y + bi.y, p1.x + bi.z, p1.y + bi.w);
        if (MODE == 0) {
            int b = r >> 10, t = r & 1023;
            *(float4*)(g_gi + ((size_t)t * Bb + b) * Gg + n) = o;
        } else {
            int t = r >> 6, b = r & 63;
            *(float4*)(Cout + ((size_t)b * Tt + t) * Oo + n) = o;
        }
    }
}

// ---------------------------------------------------------------------------
// Grid barrier (128 co-resident CTAs; 1 CTA/SM guaranteed by smem footprint).
// ---------------------------------------------------------------------------
__device__ __forceinline__ void grid_bar(unsigned target) {
    __syncthreads();
    if (threadIdx.x == 0) {
        unsigned* pc = &g_bar_count;
        unsigned* pg = &g_bar_gen;
        unsigned cnt;
        asm volatile("atom.add.acq_rel.gpu.u32 %0,[%1],1;" : "=r"(cnt) : "l"(pc) : "memory");
        if (cnt == NCTA - 1) {
            *pc = 0u;  // safe: all arrivals for this generation are in
            asm volatile("red.add.release.gpu.u32 [%0],1;" :: "l"(pg) : "memory");
        } else {
            unsigned g;
            do {
                asm volatile("ld.acquire.gpu.u32 %0,[%1];" : "=r"(g) : "l"(pg) : "memory");
            } while (g < target);
        }
    }
    __syncthreads();
}

// ---------------------------------------------------------------------------
// Persistent GRU: 128 CTAs x 256 threads. CTA owns 8 hidden units; its W_hh
// slice (1024 x 24 floats = 96 KB) lives in smem for all 1024 steps.
// Thread = (b = tid>>2, jp = tid&3): batch b, hidden units j..j+1, all gates.
// h[t-1] streamed per step in 32-wide K chunks, cp.async double-buffered.
// ---------------------------------------------------------------------------
#define WS_FLOATS (1024 * 24)
#define HT_FLOATS (2 * 64 * 36)
#define SMEM_BYTES ((WS_FLOATS + HT_FLOATS) * 4)

__global__ __launch_bounds__(256) void gru_persist(const float* __restrict__ Whh,
                                                   const float* __restrict__ bhh,
                                                   const float* __restrict__ init)
{
    extern __shared__ float sm[];
    float* Ws = sm;                    // [k][g*8 + u], 1024 x 24
    float* Ht = sm + WS_FLOATS;        // [buf][b][36], rows padded

    const int tid = threadIdx.x;
    const int b = tid >> 2, jp = tid & 3;
    const int j0 = blockIdx.x * 8;
    const int j = j0 + jp * 2;

    // Load W_hh slice once: Ws[k*24 + g*8 + part*4 .. +3]
    for (int i = tid; i < 1024 * 6; i += 256) {
        int k = i / 6, q = i - k * 6, g = q >> 1, part = q & 1;
        *(float4*)&Ws[k * 24 + g * 8 + part * 4] =
            *(const float4*)(Whh + (size_t)k * Gg + g * Hh + j0 + part * 4);
    }
    const float2 br = *(const float2*)(bhh + j);
    const float2 bz = *(const float2*)(bhh + Hh + j);
    const float2 bn = *(const float2*)(bhh + 2 * Hh + j);
    __syncthreads();

    for (int t = 0; t < Tt; ++t) {
        const float* hprev = t ? (g_h + (size_t)(t - 1) * Bb * Hh) : init;
        float* hout = g_h + (size_t)t * Bb * Hh;
        const float* gib = g_gi + (size_t)t * Bb * Gg + (size_t)b * Gg;

        u64 ar = 0ull, az = 0ull, an = 0ull;

        auto load_chunk = [&](int c, int buf) {
            #pragma unroll
            for (int i = 0; i < 2; i++) {
                int idx = tid + i * 256;          // 512 f4 = 64 b x 8 quads
                int bb = idx >> 3, kq = idx & 7;
                cp16(&Ht[buf * 64 * 36 + bb * 36 + kq * 4],
                     hprev + (size_t)bb * Hh + c * 32 + kq * 4);
            }
            asm volatile("cp.async.commit_group;");
        };

        load_chunk(0, 0);

        // Prefetch epilogue operands (long-latency; consumed after k loop)
        float2 ir  = *(const float2*)(gib + j);
        float2 iz  = *(const float2*)(gib + Hh + j);
        float2 inn = *(const float2*)(gib + 2 * Hh + j);
        float2 hp  = *(const float2*)(hprev + (size_t)b * Hh + j);

        for (int c = 0; c < 32; ++c) {
            if (c < 31) {
                load_chunk(c + 1, (c + 1) & 1);
                asm volatile("cp.async.wait_group 1;");
            } else {
                asm volatile("cp.async.wait_group 0;");
            }
            __syncthreads();
            const float* hr = &Ht[(c & 1) * 64 * 36 + b * 36];
            const float* wr = &Ws[(size_t)c * 32 * 24];
            #pragma unroll
            for (int kk = 0; kk < 32; kk += 4) {
                float4 h4 = *(const float4*)(hr + kk);
                float hv[4] = {h4.x, h4.y, h4.z, h4.w};
                #pragma unroll
                for (int u = 0; u < 4; u++) {
                    u64 hd = pk2(hv[u], hv[u]);
                    const float* wk = wr + (kk + u) * 24 + jp * 2;
                    f2(ar, hd, *(const u64*)(wk));
                    f2(az, hd, *(const u64*)(wk + 8));
                    f2(an, hd, *(const u64*)(wk + 16));
                }
            }
            __syncthreads();
        }

        float2 sr = up2(ar), sz = up2(az), sn = up2(an);
        float r0 = sigm(ir.x + sr.x + br.x);
        float r1 = sigm(ir.y + sr.y + br.y);
        float z0 = sigm(iz.x + sz.x + bz.x);
        float z1 = sigm(iz.y + sz.y + bz.y);
        float n0 = tanhf(inn.x + r0 * (sn.x + bn.x));
        float n1 = tanhf(inn.y + r1 * (sn.y + bn.y));
        float2 hn;
        hn.x = (1.0f - z0) * n0 + z0 * hp.x;
        hn.y = (1.0f - z1) * n1 + z1 * hp.y;
        *(float2*)(hout + (size_t)b * Hh + j) = hn;

        grid_bar((unsigned)(t + 1));
    }
}

extern "C" void kernel_launch(void* const* d_in, const int* in_sizes, int n_in,
                              void* d_out, int out_size)
{
    const float* X    = (const float*)d_in[0];
    const float* init = (const float*)d_in[1];
    const float* Wih  = (const float*)d_in[2];
    const float* Whh  = (const float*)d_in[3];
    const float* bih  = (const float*)d_in[4];
    const float* bhh  = (const float*)d_in[5];
    const float* Wout = (const float*)d_in[6];
    const float* bout = (const float*)d_in[7];
    float* out = (float*)d_out;

    static bool attr_set = false;
    if (!attr_set) {
        cudaFuncSetAttribute(gru_persist,
                             cudaFuncAttributeMaxDynamicSharedMemorySize, SMEM_BYTES);
        attr_set = true;
    }

    init_bar<<<1, 1>>>();

    // Phase 1: gi = X @ W_ih + b_ih   (M=65536, N=3072, K=512)
    sgemm<512, 0><<<dim3(Gg / 64, (Bb * Tt) / 128), 256>>>(X, Wih, bih, nullptr);

    // Phase 2: all 1024 GRU steps in one persistent kernel
    gru_persist<<<NCTA, 256, SMEM_BYTES>>>(Whh, bhh, init);

    // Phase 3: out = h @ W_out + b_out  (M=65536, N=256, K=1024)
    sgemm<1024, 1><<<dim3(Oo / 64, (Bb * Tt) / 128), 256>>>(nullptr, Wout, bout, out);
}

// round 6
// speedup vs baseline: 2.0230x; 2.0230x over previous
#include <cuda_runtime.h>
#include <cstdint>

#define Tt 1024
#define Bb 64
#define Ii 512
#define Hh 1024
#define Gg 3072
#define Oo 256
#define NCTA 128

// scratch (device globals = allowed scratch)
__device__ float g_gi[(size_t)Tt * Bb * Gg];        // [t][b][g]
__device__ float g_h [(size_t)(Tt + 1) * Hh * Bb];  // [t][k][b], slot 0 = init^T
__device__ unsigned g_bar_count;
__device__ unsigned g_bar_gen;

typedef unsigned long long u64;

__device__ __forceinline__ u64 pk2(float x, float y) {
    u64 r; asm("mov.b64 %0,{%1,%2};" : "=l"(r) : "f"(x), "f"(y)); return r;
}
__device__ __forceinline__ void f2(u64& d, u64 a, u64 b) {
    asm("fma.rn.f32x2 %0,%1,%2,%0;" : "+l"(d) : "l"(a), "l"(b));
}
__device__ __forceinline__ u64 add2(u64 a, u64 b) {
    u64 d; asm("add.rn.f32x2 %0,%1,%2;" : "=l"(d) : "l"(a), "l"(b)); return d;
}
__device__ __forceinline__ float2 up2(u64 a) {
    float2 f; asm("mov.b64 {%0,%1},%2;" : "=f"(f.x), "=f"(f.y) : "l"(a)); return f;
}
__device__ __forceinline__ float sigm(float x) { return 1.0f / (1.0f + __expf(-x)); }

__device__ __forceinline__ void cp16(void* smem, const void* g) {
    uint32_t s = (uint32_t)__cvta_generic_to_shared(smem);
    asm volatile("cp.async.cg.shared.global [%0], [%1], 16;" :: "r"(s), "l"(g));
}

__global__ void init_bar() { g_bar_count = 0u; g_bar_gen = 0u; }

// transpose init [b][k] -> g_h slot 0 [k][b]
__global__ void h0_init(const float* __restrict__ init) {
    int i = blockIdx.x * 256 + threadIdx.x;   // 65536
    int k = i >> 6, b = i & 63;
    g_h[(size_t)k * Bb + b] = init[(size_t)b * Hh + k];
}

// ---------------------------------------------------------------------------
// SGEMM: C[M,N] = A[M,K] @ W[K,N] + bias.  BM=128, BN=64, BK=16, 256 threads,
// thread-tile 8m x 4n (n packed as f32x2 pairs).
// MODE 0: A=X [M=b*1024+t, K=512], W_ih ldw=3072, writes g_gi[t][b][g].
// MODE 1: A=g_h transposed [t][k][b] (m=t*64+b), K=1024, ldw=256, writes out.
// ---------------------------------------------------------------------------
template <int K, int MODE>
__global__ __launch_bounds__(256) void sgemm(const float* __restrict__ Ain,
                                             const float* __restrict__ W,
                                             const float* __restrict__ bias,
                                             float* __restrict__ Cout)
{
    __shared__ float As[16][132];
    __shared__ float Bs[16][64];
    const int ldw = (MODE == 0) ? Gg : Oo;
    const int m0 = blockIdx.y * 128, n0 = blockIdx.x * 64;
    const int tid = threadIdx.x;
    const int tn = tid & 15, tm = tid >> 4;

    u64 acc[8][2];
    #pragma unroll
    for (int m = 0; m < 8; m++) { acc[m][0] = 0ull; acc[m][1] = 0ull; }

    for (int k0 = 0; k0 < K; k0 += 16) {
        if (MODE == 0) {
            #pragma unroll
            for (int i = 0; i < 2; i++) {
                int idx = tid + i * 256;            // 512 float4 = 128 rows x 4
                int r = idx >> 2, kq = idx & 3;
                float4 v = *(const float4*)(Ain + (size_t)(m0 + r) * K + k0 + kq * 4);
                As[kq * 4 + 0][r] = v.x; As[kq * 4 + 1][r] = v.y;
                As[kq * 4 + 2][r] = v.z; As[kq * 4 + 3][r] = v.w;
            }
        } else {
            // tile = 2 t-slices x 16 k x 64 b from g_h[t+1][k][b]
            #pragma unroll
            for (int i = 0; i < 2; i++) {
                int idx = tid + i * 256;            // 512 float4
                int tsl = idx >> 8, k = (idx >> 4) & 15, q = idx & 15;
                float4 v = *(const float4*)(g_h +
                    (size_t)((m0 >> 6) + tsl + 1) * (Hh * Bb) + (size_t)(k0 + k) * Bb + q * 4);
                *(float4*)&As[k][tsl * 64 + q * 4] = v;
            }
        }
        {
            int r = tid >> 4, gq = tid & 15;        // 16 rows x 16 float4
            *(float4*)&Bs[r][gq * 4] =
                *(const float4*)(W + (size_t)(k0 + r) * ldw + n0 + gq * 4);
        }
        __syncthreads();
        #pragma unroll
        for (int k = 0; k < 16; k++) {
            float4 a0 = *(float4*)&As[k][tm * 8];
            float4 a1 = *(float4*)&As[k][tm * 8 + 4];
            u64 b0 = *(u64*)&Bs[k][tn * 4];
            u64 b1 = *(u64*)&Bs[k][tn * 4 + 2];
            float av[8] = {a0.x, a0.y, a0.z, a0.w, a1.x, a1.y, a1.z, a1.w};
            #pragma unroll
            for (int m = 0; m < 8; m++) {
                u64 ad = pk2(av[m], av[m]);
                f2(acc[m][0], ad, b0);
                f2(acc[m][1], ad, b1);
            }
        }
        __syncthreads();
    }

    const int n = n0 + tn * 4;
    float4 bi = *(const float4*)(bias + n);
    #pragma unroll
    for (int m = 0; m < 8; m++) {
        int r = m0 + tm * 8 + m;
        float2 p0 = up2(acc[m][0]), p1 = up2(acc[m][1]);
        float4 o = make_float4(p0.x + bi.x, p0.y + bi.y, p1.x + bi.z, p1.y + bi.w);
        if (MODE == 0) {
            int b = r >> 10, t = r & 1023;
            *(float4*)(g_gi + ((size_t)t * Bb + b) * Gg + n) = o;
        } else {
            int t = r >> 6, b = r & 63;
            *(float4*)(Cout + ((size_t)b * Tt + t) * Oo + n) = o;
        }
    }
}

// ---------------------------------------------------------------------------
// Grid barrier (128 co-resident CTAs, 1 CTA/SM by smem footprint).
// ---------------------------------------------------------------------------
__device__ __forceinline__ void grid_bar(unsigned target) {
    __syncthreads();
    if (threadIdx.x == 0) {
        unsigned* pc = &g_bar_count;
        unsigned* pg = &g_bar_gen;
        unsigned cnt;
        asm volatile("atom.add.acq_rel.gpu.u32 %0,[%1],1;" : "=r"(cnt) : "l"(pc) : "memory");
        if (cnt == NCTA - 1) {
            *pc = 0u;
            asm volatile("red.add.release.gpu.u32 [%0],1;" :: "l"(pg) : "memory");
        } else {
            unsigned g;
            do {
                asm volatile("ld.acquire.gpu.u32 %0,[%1];" : "=r"(g) : "l"(pg) : "memory");
            } while (g < target);
        }
    }
    __syncthreads();
}

// ---------------------------------------------------------------------------
// Persistent GRU. 128 CTAs x 256 thr. CTA owns 8 hidden units, W slice in smem.
// Thread = (bq:4 | ks:2 | jp:2): 4 batches (b0=bq*4), K-quarter ks, unit pair
// j=j0+jp*2. Per k: 1 LDS.128(h)+4 pk2+3 LDS.64(W pair, direct B-op)+12 FFMA2.
// K-split reduced with 2x shfl.bfly (ks = lane bits 2..3).
// h streamed [k][b] in 8 chunks of 128 k, cp.async double-buffered.
// ---------------------------------------------------------------------------
#define HT_STRIDE 72
#define CHUNK_K 128
#define NCHUNK 8
#define WS_F (1024 * 24)
#define HT_F (2 * CHUNK_K * HT_STRIDE)
#define SMEMB ((WS_F + HT_F) * 4)

__global__ __launch_bounds__(256) void gru_persist(const float* __restrict__ Whh,
                                                   const float* __restrict__ bhh)
{
    extern __shared__ float sm[];
    float* Ws = sm;              // [k][g*8 + u] 1024 x 24
    float* Ht = sm + WS_F;       // [buf][k][72]

    const int tid = threadIdx.x;
    const int bq = tid >> 4, ks = (tid >> 2) & 3, jp = tid & 3;
    const int b0 = bq * 4;
    const int j0 = blockIdx.x * 8, j = j0 + jp * 2;

    for (int i = tid; i < 1024 * 6; i += 256) {
        int k = i / 6, q = i - k * 6, g = q >> 1, part = q & 1;
        *(float4*)&Ws[k * 24 + g * 8 + part * 4] =
            *(const float4*)(Whh + (size_t)k * Gg + g * Hh + j0 + part * 4);
    }
    const float2 br = *(const float2*)(bhh + j);
    const float2 bz = *(const float2*)(bhh + Hh + j);
    const float2 bn = *(const float2*)(bhh + 2 * Hh + j);
    __syncthreads();

    for (int t = 0; t < Tt; ++t) {
        const float* hprev = g_h + (size_t)t * (Hh * Bb);
        float* hout       = g_h + (size_t)(t + 1) * (Hh * Bb);

        // chunk = 128 k x 64 b = 8192 floats = 2048 float4; src rows (64 f)
        // are contiguous in [k][b], dst rows padded to 72 floats.
        auto load_chunk = [&](int c, int buf) {
            const float* src = hprev + c * (CHUNK_K * Bb);
            float* dstb = Ht + buf * (CHUNK_K * HT_STRIDE);
            #pragma unroll
            for (int i = 0; i < 8; i++) {
                int f4 = i * 256 + tid;            // 2048 float4 = 128 k x 16
                int row = f4 >> 4, q = f4 & 15;
                cp16(dstb + row * HT_STRIDE + q * 4, src + f4 * 4);
            }
            asm volatile("cp.async.commit_group;");
        };
        load_chunk(0, 0);

        // prefetch epilogue operands (consumed after the k loop)
        float2 gir[4], giz[4], gin[4];
        float4 hpj, hpj1;
        if (ks == 0) {
            const float* gp = g_gi + ((size_t)t * Bb + b0) * Gg;
            #pragma unroll
            for (int b = 0; b < 4; b++) {
                gir[b] = *(const float2*)(gp + (size_t)b * Gg + j);
                giz[b] = *(const float2*)(gp + (size_t)b * Gg + Hh + j);
                gin[b] = *(const float2*)(gp + (size_t)b * Gg + 2 * Hh + j);
            }
            hpj  = *(const float4*)(hprev + (size_t)j * Bb + b0);
            hpj1 = *(const float4*)(hprev + (size_t)(j + 1) * Bb + b0);
        }

        u64 acc[3][4];
        #pragma unroll
        for (int g = 0; g < 3; g++)
            #pragma unroll
            for (int b = 0; b < 4; b++) acc[g][b] = 0ull;

        for (int c = 0; c < NCHUNK; ++c) {
            if (c < NCHUNK - 1) {
                load_chunk(c + 1, (c + 1) & 1);
                asm volatile("cp.async.wait_group 1;");
            } else {
                asm volatile("cp.async.wait_group 0;");
            }
            __syncthreads();
            const float* hb = Ht + (c & 1) * (CHUNK_K * HT_STRIDE) + ks * HT_STRIDE + b0;
            const float* wp = Ws + (c * CHUNK_K + ks) * 24 + jp * 2;
            #pragma unroll 8
            for (int kk = 0; kk < 32; ++kk) {
                const float* hq = hb + kk * (4 * HT_STRIDE);
                float h0 = hq[0], h1 = hq[1], h2 = hq[2], h3 = hq[3];
                u64 hd0 = pk2(h0, h0), hd1 = pk2(h1, h1);
                u64 hd2 = pk2(h2, h2), hd3 = pk2(h3, h3);
                const float* wq = wp + kk * 96;
                u64 wr = *(const u64*)(wq);
                u64 wz = *(const u64*)(wq + 8);
                u64 wn = *(const u64*)(wq + 16);
                f2(acc[0][0], hd0, wr); f2(acc[0][1], hd1, wr);
                f2(acc[0][2], hd2, wr); f2(acc[0][3], hd3, wr);
                f2(acc[1][0], hd0, wz); f2(acc[1][1], hd1, wz);
                f2(acc[1][2], hd2, wz); f2(acc[1][3], hd3, wz);
                f2(acc[2][0], hd0, wn); f2(acc[2][1], hd1, wn);
                f2(acc[2][2], hd2, wn); f2(acc[2][3], hd3, wn);
            }
            __syncthreads();
        }

        // reduce K-split over ks (lane bits 2..3)
        #pragma unroll
        for (int g = 0; g < 3; g++)
            #pragma unroll
            for (int b = 0; b < 4; b++) {
                u64 v = acc[g][b];
                v = add2(v, __shfl_xor_sync(0xffffffffu, v, 4));
                v = add2(v, __shfl_xor_sync(0xffffffffu, v, 8));
                acc[g][b] = v;
            }

        if (ks == 0) {
            float hj[4], hj1[4];
            const float hpv[2][4] = {{hpj.x, hpj.y, hpj.z, hpj.w},
                                     {hpj1.x, hpj1.y, hpj1.z, hpj1.w}};
            #pragma unroll
            for (int b = 0; b < 4; b++) {
                float2 sr = up2(acc[0][b]), sz = up2(acc[1][b]), sn = up2(acc[2][b]);
                float r0 = sigm(gir[b].x + sr.x + br.x);
                float r1 = sigm(gir[b].y + sr.y + br.y);
                float z0 = sigm(giz[b].x + sz.x + bz.x);
                float z1 = sigm(giz[b].y + sz.y + bz.y);
                float n0 = tanhf(gin[b].x + r0 * (sn.x + bn.x));
                float n1 = tanhf(gin[b].y + r1 * (sn.y + bn.y));
                hj[b]  = (1.0f - z0) * n0 + z0 * hpv[0][b];
                hj1[b] = (1.0f - z1) * n1 + z1 * hpv[1][b];
            }
            *(float4*)(hout + (size_t)j * Bb + b0) =
                make_float4(hj[0], hj[1], hj[2], hj[3]);
            *(float4*)(hout + (size_t)(j + 1) * Bb + b0) =
                make_float4(hj1[0], hj1[1], hj1[2], hj1[3]);
        }
        grid_bar((unsigned)(t + 1));
    }
}

extern "C" void kernel_launch(void* const* d_in, const int* in_sizes, int n_in,
                              void* d_out, int out_size)
{
    const float* X    = (const float*)d_in[0];
    const float* init = (const float*)d_in[1];
    const float* Wih  = (const float*)d_in[2];
    const float* Whh  = (const float*)d_in[3];
    const float* bih  = (const float*)d_in[4];
    const float* bhh  = (const float*)d_in[5];
    const float* Wout = (const float*)d_in[6];
    const float* bout = (const float*)d_in[7];
    float* out = (float*)d_out;

    cudaFuncSetAttribute(gru_persist,
                         cudaFuncAttributeMaxDynamicSharedMemorySize, SMEMB);

    init_bar<<<1, 1>>>();
    h0_init<<<256, 256>>>(init);

    // Phase 1: gi = X @ W_ih + b_ih   (M=65536, N=3072, K=512)
    sgemm<512, 0><<<dim3(Gg / 64, (Bb * Tt) / 128), 256>>>(X, Wih, bih, nullptr);

    // Phase 2: all 1024 GRU steps in one persistent kernel
    gru_persist<<<NCTA, 256, SMEMB>>>(Whh, bhh);

    // Phase 3: out = h @ W_out + b_out  (M=65536, N=256, K=1024)
    sgemm<1024, 1><<<dim3(Oo / 64, (Bb * Tt) / 128), 256>>>(nullptr, Wout, bout, out);
}

// round 7
// speedup vs baseline: 2.0434x; 1.0101x over previous
#include <cuda_runtime.h>
#include <cstdint>

#define Tt 1024
#define Bb 64
#define Ii 512
#define Hh 1024
#define Gg 3072
#define Oo 256
#define NCTA 128

// scratch (device globals = allowed scratch)
__device__ float g_gi[(size_t)Tt * Bb * Gg];        // [t][b][g]
__device__ float g_h [(size_t)(Tt + 1) * Hh * Bb];  // [t][k][b], slot 0 = init^T
__device__ unsigned g_bar_count;
__device__ unsigned g_bar_gen;

typedef unsigned long long u64;

__device__ __forceinline__ u64 pk2(float x, float y) {
    u64 r; asm("mov.b64 %0,{%1,%2};" : "=l"(r) : "f"(x), "f"(y)); return r;
}
__device__ __forceinline__ void f2(u64& d, u64 a, u64 b) {
    asm("fma.rn.f32x2 %0,%1,%2,%0;" : "+l"(d) : "l"(a), "l"(b));
}
__device__ __forceinline__ u64 add2(u64 a, u64 b) {
    u64 d; asm("add.rn.f32x2 %0,%1,%2;" : "=l"(d) : "l"(a), "l"(b)); return d;
}
__device__ __forceinline__ float2 up2(u64 a) {
    float2 f; asm("mov.b64 {%0,%1},%2;" : "=f"(f.x), "=f"(f.y) : "l"(a)); return f;
}
__device__ __forceinline__ float sigm(float x) { return 1.0f / (1.0f + __expf(-x)); }

__device__ __forceinline__ void cp16(void* smem, const void* g) {
    uint32_t s = (uint32_t)__cvta_generic_to_shared(smem);
    asm volatile("cp.async.cg.shared.global [%0], [%1], 16;" :: "r"(s), "l"(g));
}

__global__ void init_bar() { g_bar_count = 0u; g_bar_gen = 0u; }

// transpose init [b][k] -> g_h slot 0 [k][b]
__global__ void h0_init(const float* __restrict__ init) {
    int i = blockIdx.x * 256 + threadIdx.x;   // 65536
    int k = i >> 6, b = i & 63;
    g_h[(size_t)k * Bb + b] = init[(size_t)b * Hh + k];
}

// ---------------------------------------------------------------------------
// SGEMM: C[M,N] = A[M,K] @ W[K,N] + bias.  BM=128, BN=64, BK=16, 256 threads,
// thread-tile 8m x 4n (n packed as f32x2 pairs).
// MODE 0: A=X [M=b*1024+t, K=512], W_ih ldw=3072, writes g_gi[t][b][g].
// MODE 1: A=g_h transposed [t][k][b] (m=t*64+b), K=1024, ldw=256, writes out.
// ---------------------------------------------------------------------------
template <int K, int MODE>
__global__ __launch_bounds__(256) void sgemm(const float* __restrict__ Ain,
                                             const float* __restrict__ W,
                                             const float* __restrict__ bias,
                                             float* __restrict__ Cout)
{
    __shared__ float As[16][132];
    __shared__ float Bs[16][64];
    const int ldw = (MODE == 0) ? Gg : Oo;
    const int m0 = blockIdx.y * 128, n0 = blockIdx.x * 64;
    const int tid = threadIdx.x;
    const int tn = tid & 15, tm = tid >> 4;

    u64 acc[8][2];
    #pragma unroll
    for (int m = 0; m < 8; m++) { acc[m][0] = 0ull; acc[m][1] = 0ull; }

    for (int k0 = 0; k0 < K; k0 += 16) {
        if (MODE == 0) {
            #pragma unroll
            for (int i = 0; i < 2; i++) {
                int idx = tid + i * 256;            // 512 float4 = 128 rows x 4
                int r = idx >> 2, kq = idx & 3;
                float4 v = *(const float4*)(Ain + (size_t)(m0 + r) * K + k0 + kq * 4);
                As[kq * 4 + 0][r] = v.x; As[kq * 4 + 1][r] = v.y;
                As[kq * 4 + 2][r] = v.z; As[kq * 4 + 3][r] = v.w;
            }
        } else {
            // tile = 2 t-slices x 16 k x 64 b from g_h[t+1][k][b]
            #pragma unroll
            for (int i = 0; i < 2; i++) {
                int idx = tid + i * 256;            // 512 float4
                int tsl = idx >> 8, k = (idx >> 4) & 15, q = idx & 15;
                float4 v = *(const float4*)(g_h +
                    (size_t)((m0 >> 6) + tsl + 1) * (Hh * Bb) + (size_t)(k0 + k) * Bb + q * 4);
                *(float4*)&As[k][tsl * 64 + q * 4] = v;
            }
        }
        {
            int r = tid >> 4, gq = tid & 15;        // 16 rows x 16 float4
            *(float4*)&Bs[r][gq * 4] =
                *(const float4*)(W + (size_t)(k0 + r) * ldw + n0 + gq * 4);
        }
        __syncthreads();
        #pragma unroll
        for (int k = 0; k < 16; k++) {
            float4 a0 = *(float4*)&As[k][tm * 8];
            float4 a1 = *(float4*)&As[k][tm * 8 + 4];
            u64 b0 = *(u64*)&Bs[k][tn * 4];
            u64 b1 = *(u64*)&Bs[k][tn * 4 + 2];
            float av[8] = {a0.x, a0.y, a0.z, a0.w, a1.x, a1.y, a1.z, a1.w};
            #pragma unroll
            for (int m = 0; m < 8; m++) {
                u64 ad = pk2(av[m], av[m]);
                f2(acc[m][0], ad, b0);
                f2(acc[m][1], ad, b1);
            }
        }
        __syncthreads();
    }

    const int n = n0 + tn * 4;
    float4 bi = *(const float4*)(bias + n);
    #pragma unroll
    for (int m = 0; m < 8; m++) {
        int r = m0 + tm * 8 + m;
        float2 p0 = up2(acc[m][0]), p1 = up2(acc[m][1]);
        float4 o = make_float4(p0.x + bi.x, p0.y + bi.y, p1.x + bi.z, p1.y + bi.w);
        if (MODE == 0) {
            int b = r >> 10, t = r & 1023;
            *(float4*)(g_gi + ((size_t)t * Bb + b) * Gg + n) = o;
        } else {
            int t = r >> 6, b = r & 63;
            *(float4*)(Cout + ((size_t)b * Tt + t) * Oo + n) = o;
        }
    }
}

// ---------------------------------------------------------------------------
// Grid barrier (128 co-resident CTAs, 1 CTA/SM by smem footprint).
// ---------------------------------------------------------------------------
__device__ __forceinline__ void grid_bar(unsigned target) {
    __syncthreads();
    if (threadIdx.x == 0) {
        unsigned* pc = &g_bar_count;
        unsigned* pg = &g_bar_gen;
        unsigned cnt;
        asm volatile("atom.add.acq_rel.gpu.u32 %0,[%1],1;" : "=r"(cnt) : "l"(pc) : "memory");
        if (cnt == NCTA - 1) {
            *pc = 0u;
            asm volatile("red.add.release.gpu.u32 [%0],1;" :: "l"(pg) : "memory");
        } else {
            unsigned g;
            do {
                asm volatile("ld.acquire.gpu.u32 %0,[%1];" : "=r"(g) : "l"(pg) : "memory");
            } while (g < target);
        }
    }
    __syncthreads();
}

// ---------------------------------------------------------------------------
// Persistent GRU. 128 CTAs x 512 thr (4 warps/SMSP for latency hiding).
// CTA owns 8 hidden units; its W_hh slice (1024x24 f) lives in smem.
// Thread = (bq = tid>>5, ks = (tid>>2)&7, jp = tid&3): 4 batches b0=bq*4,
// K-eighth ks (k = 8*kk + ks), unit pair j = j0 + jp*2.
// Per k: 1 LDS.128(h) + 4 pk2 + 3 LDS.64(W pair, direct B-op) + 12 FFMA2.
// K-split reduced with 3x shfl.bfly (ks = lane bits 2..4).
// h streamed [k][b] in 8 chunks of 128 k, cp.async double-buffered.
// ---------------------------------------------------------------------------
#define HT_STRIDE 72
#define CHUNK_K 128
#define NCHUNK 8
#define WS_F (1024 * 24)
#define HT_F (2 * CHUNK_K * HT_STRIDE)
#define SMEMB ((WS_F + HT_F) * 4)

__global__ __launch_bounds__(512) void gru_persist(const float* __restrict__ Whh,
                                                   const float* __restrict__ bhh)
{
    extern __shared__ float sm[];
    float* Ws = sm;              // [k][g*8 + u] 1024 x 24
    float* Ht = sm + WS_F;       // [buf][k][72]

    const int tid = threadIdx.x;
    const int bq = tid >> 5, ks = (tid >> 2) & 7, jp = tid & 3;
    const int b0 = bq * 4;
    const int j0 = blockIdx.x * 8, j = j0 + jp * 2;

    for (int i = tid; i < 1024 * 6; i += 512) {
        int k = i / 6, q = i - k * 6, g = q >> 1, part = q & 1;
        *(float4*)&Ws[k * 24 + g * 8 + part * 4] =
            *(const float4*)(Whh + (size_t)k * Gg + g * Hh + j0 + part * 4);
    }
    const float2 br = *(const float2*)(bhh + j);
    const float2 bz = *(const float2*)(bhh + Hh + j);
    const float2 bn = *(const float2*)(bhh + 2 * Hh + j);
    __syncthreads();

    for (int t = 0; t < Tt; ++t) {
        const float* hprev = g_h + (size_t)t * (Hh * Bb);
        float* hout       = g_h + (size_t)(t + 1) * (Hh * Bb);

        // chunk = 128 k x 64 b = 2048 float4; src rows (64 f) contiguous in
        // [k][b], dst rows padded to 72 floats.
        auto load_chunk = [&](int c, int buf) {
            const float* src = hprev + c * (CHUNK_K * Bb);
            float* dstb = Ht + buf * (CHUNK_K * HT_STRIDE);
            #pragma unroll
            for (int i = 0; i < 4; i++) {
                int f4 = i * 512 + tid;            // 2048 float4 = 128 k x 16
                int row = f4 >> 4, q = f4 & 15;
                cp16(dstb + row * HT_STRIDE + q * 4, src + f4 * 4);
            }
            asm volatile("cp.async.commit_group;");
        };
        load_chunk(0, 0);

        // prefetch epilogue operands (consumed after the k loop)
        float2 gir[4], giz[4], gin[4];
        float4 hpj, hpj1;
        if (ks == 0) {
            const float* gp = g_gi + ((size_t)t * Bb + b0) * Gg;
            #pragma unroll
            for (int b = 0; b < 4; b++) {
                gir[b] = *(const float2*)(gp + (size_t)b * Gg + j);
                giz[b] = *(const float2*)(gp + (size_t)b * Gg + Hh + j);
                gin[b] = *(const float2*)(gp + (size_t)b * Gg + 2 * Hh + j);
            }
            hpj  = *(const float4*)(hprev + (size_t)j * Bb + b0);
            hpj1 = *(const float4*)(hprev + (size_t)(j + 1) * Bb + b0);
        }

        u64 acc[3][4];
        #pragma unroll
        for (int g = 0; g < 3; g++)
            #pragma unroll
            for (int b = 0; b < 4; b++) acc[g][b] = 0ull;

        for (int c = 0; c < NCHUNK; ++c) {
            if (c < NCHUNK - 1) {
                load_chunk(c + 1, (c + 1) & 1);
                asm volatile("cp.async.wait_group 1;");
            } else {
                asm volatile("cp.async.wait_group 0;");
            }
            __syncthreads();
            const float* hb = Ht + (c & 1) * (CHUNK_K * HT_STRIDE) + ks * HT_STRIDE + b0;
            const float* wp = Ws + (c * CHUNK_K + ks) * 24 + jp * 2;
            #pragma unroll
            for (int kk = 0; kk < 16; ++kk) {
                const float* hq = hb + kk * (8 * HT_STRIDE);
                float h0 = hq[0], h1 = hq[1], h2 = hq[2], h3 = hq[3];
                u64 hd0 = pk2(h0, h0), hd1 = pk2(h1, h1);
                u64 hd2 = pk2(h2, h2), hd3 = pk2(h3, h3);
                const float* wq = wp + kk * (8 * 24);
                u64 wr = *(const u64*)(wq);
                u64 wz = *(const u64*)(wq + 8);
                u64 wn = *(const u64*)(wq + 16);
                f2(acc[0][0], hd0, wr); f2(acc[0][1], hd1, wr);
                f2(acc[0][2], hd2, wr); f2(acc[0][3], hd3, wr);
                f2(acc[1][0], hd0, wz); f2(acc[1][1], hd1, wz);
                f2(acc[1][2], hd2, wz); f2(acc[1][3], hd3, wz);
                f2(acc[2][0], hd0, wn); f2(acc[2][1], hd1, wn);
                f2(acc[2][2], hd2, wn); f2(acc[2][3], hd3, wn);
            }
            __syncthreads();
        }

        // reduce K-split over ks (lane bits 2..4)
        #pragma unroll
        for (int g = 0; g < 3; g++)
            #pragma unroll
            for (int b = 0; b < 4; b++) {
                u64 v = acc[g][b];
                v = add2(v, __shfl_xor_sync(0xffffffffu, v, 4));
                v = add2(v, __shfl_xor_sync(0xffffffffu, v, 8));
                v = add2(v, __shfl_xor_sync(0xffffffffu, v, 16));
                acc[g][b] = v;
            }

        if (ks == 0) {
            float hj[4], hj1[4];
            const float hpv[2][4] = {{hpj.x, hpj.y, hpj.z, hpj.w},
                                     {hpj1.x, hpj1.y, hpj1.z, hpj1.w}};
            #pragma unroll
            for (int b = 0; b < 4; b++) {
                float2 sr = up2(acc[0][b]), sz = up2(acc[1][b]), sn = up2(acc[2][b]);
                float r0 = sigm(gir[b].x + sr.x + br.x);
                float r1 = sigm(gir[b].y + sr.y + br.y);
                float z0 = sigm(giz[b].x + sz.x + bz.x);
                float z1 = sigm(giz[b].y + sz.y + bz.y);
                float n0 = tanhf(gin[b].x + r0 * (sn.x + bn.x));
                float n1 = tanhf(gin[b].y + r1 * (sn.y + bn.y));
                hj[b]  = (1.0f - z0) * n0 + z0 * hpv[0][b];
                hj1[b] = (1.0f - z1) * n1 + z1 * hpv[1][b];
            }
            *(float4*)(hout + (size_t)j * Bb + b0) =
                make_float4(hj[0], hj[1], hj[2], hj[3]);
            *(float4*)(hout + (size_t)(j + 1) * Bb + b0) =
                make_float4(hj1[0], hj1[1], hj1[2], hj1[3]);
        }
        grid_bar((unsigned)(t + 1));
    }
}

extern "C" void kernel_launch(void* const* d_in, const int* in_sizes, int n_in,
                              void* d_out, int out_size)
{
    const float* X    = (const float*)d_in[0];
    const float* init = (const float*)d_in[1];
    const float* Wih  = (const float*)d_in[2];
    const float* Whh  = (const float*)d_in[3];
    const float* bih  = (const float*)d_in[4];
    const float* bhh  = (const float*)d_in[5];
    const float* Wout = (const float*)d_in[6];
    const float* bout = (const float*)d_in[7];
    float* out = (float*)d_out;

    cudaFuncSetAttribute(gru_persist,
                         cudaFuncAttributeMaxDynamicSharedMemorySize, SMEMB);

    init_bar<<<1, 1>>>();
    h0_init<<<256, 256>>>(init);

    // Phase 1: gi = X @ W_ih + b_ih   (M=65536, N=3072, K=512)
    sgemm<512, 0><<<dim3(Gg / 64, (Bb * Tt) / 128), 256>>>(X, Wih, bih, nullptr);

    // Phase 2: all 1024 GRU steps in one persistent kernel
    gru_persist<<<NCTA, 512, SMEMB>>>(Whh, bhh);

    // Phase 3: out = h @ W_out + b_out  (M=65536, N=256, K=1024)
    sgemm<1024, 1><<<dim3(Oo / 64, (Bb * Tt) / 128), 256>>>(nullptr, Wout, bout, out);
}